// round 1
// baseline (speedup 1.0000x reference)
#include <cuda_runtime.h>

// ---------------- problem constants ----------------
#define T_TOKENS 16384      // b*s = 4*4096
#define SEQ      4096
#define DIM      2048
#define QLORA    1536
#define NH       16
#define DN       128
#define DR       64
#define DV       128
#define KVL      512
#define HD       192        // DN+DR
#define QDIM     3072       // NH*HD
#define KVA      576        // KVL+DR
#define KVUPD    4096       // NH*(DN+DV)

// ---------------- scratch (no allocs allowed) ----------------
__device__ float g_qa  [(size_t)T_TOKENS * QLORA];
__device__ float g_q   [(size_t)T_TOKENS * QDIM];
__device__ float g_kv  [(size_t)T_TOKENS * KVA];
__device__ float g_kvn [(size_t)T_TOKENS * KVL];
__device__ float g_kvup[(size_t)T_TOKENS * KVUPD];
__device__ float g_ctx [(size_t)T_TOKENS * (NH * DV)];

// ---------------- packed f32x2 helpers ----------------
__device__ __forceinline__ unsigned long long pack_dup(float a) {
    unsigned long long r;
    unsigned int ai = __float_as_uint(a);
    asm("mov.b64 %0, {%1, %1};" : "=l"(r) : "r"(ai));
    return r;
}
__device__ __forceinline__ void fma2(unsigned long long& c,
                                     unsigned long long a,
                                     unsigned long long b) {
    asm("fma.rn.f32x2 %0, %1, %2, %0;" : "+l"(c) : "l"(a), "l"(b));
}

// ---------------- SGEMM: C[M,N] = A[M,K] @ B[K,N], row-major ----------------
// BM=BN=128, BK=16, 256 threads, 8x8 per-thread, f32x2 packed accumulation.
// Requires: M % 128 == 0, K % 16 == 0, N % 8 == 0 (N may be non-mult of 128).
__global__ __launch_bounds__(256, 2)
void sgemm_kernel(const float* __restrict__ A, const float* __restrict__ B,
                  float* __restrict__ C, int M, int N, int K)
{
    __shared__ float As[16][132];   // transposed A tile, pad 4 for bank spread
    __shared__ float Bs[16][128];

    const int tid = threadIdx.x;
    const int tx  = tid & 15;       // n-direction (8 cols each)
    const int ty  = tid >> 4;       // m-direction (8 rows each)
    const int m0  = blockIdx.y << 7;
    const int n0  = blockIdx.x << 7;

    const int a_row = tid >> 2;          // 0..63  (x2 iterations)
    const int a_col = (tid & 3) << 2;    // 0,4,8,12
    const int b_row = tid >> 5;          // 0..7   (x2 iterations)
    const int b_col = (tid & 31) << 2;   // 0..124

    unsigned long long c2[8][4];
    #pragma unroll
    for (int i = 0; i < 8; i++)
        #pragma unroll
        for (int j = 0; j < 4; j++) c2[i][j] = 0ULL;

    for (int k0 = 0; k0 < K; k0 += 16) {
        #pragma unroll
        for (int r = 0; r < 2; r++) {
            int row = a_row + 64 * r;
            float4 av = *(const float4*)(A + (size_t)(m0 + row) * K + (k0 + a_col));
            As[a_col + 0][row] = av.x;
            As[a_col + 1][row] = av.y;
            As[a_col + 2][row] = av.z;
            As[a_col + 3][row] = av.w;
        }
        #pragma unroll
        for (int r = 0; r < 2; r++) {
            int row = b_row + 8 * r;
            int col = n0 + b_col;
            float4 bv = make_float4(0.f, 0.f, 0.f, 0.f);
            if (col < N)
                bv = *(const float4*)(B + (size_t)(k0 + row) * N + col);
            *(float4*)(&Bs[row][b_col]) = bv;
        }
        __syncthreads();

        #pragma unroll
        for (int k = 0; k < 16; k++) {
            float a[8];
            *(float4*)(&a[0]) = *(const float4*)(&As[k][ty * 8]);
            *(float4*)(&a[4]) = *(const float4*)(&As[k][ty * 8 + 4]);
            unsigned long long b2[4];
            const unsigned long long* bp =
                (const unsigned long long*)(&Bs[k][tx * 8]);
            #pragma unroll
            for (int j = 0; j < 4; j++) b2[j] = bp[j];
            #pragma unroll
            for (int i = 0; i < 8; i++) {
                unsigned long long a2 = pack_dup(a[i]);
                #pragma unroll
                for (int j = 0; j < 4; j++) fma2(c2[i][j], a2, b2[j]);
            }
        }
        __syncthreads();
    }

    const int col = n0 + tx * 8;
    if (col < N) {
        #pragma unroll
        for (int i = 0; i < 8; i++) {
            int row = m0 + ty * 8 + i;
            float2 f0 = *(float2*)&c2[i][0];
            float2 f1 = *(float2*)&c2[i][1];
            float2 f2 = *(float2*)&c2[i][2];
            float2 f3 = *(float2*)&c2[i][3];
            *(float4*)(C + (size_t)row * N + col)     = make_float4(f0.x, f0.y, f1.x, f1.y);
            *(float4*)(C + (size_t)row * N + col + 4) = make_float4(f2.x, f2.y, f3.x, f3.y);
        }
    }
}

// ---------------- RMSNorm (block per row) ----------------
__global__ void rmsnorm_kernel(const float* __restrict__ in, float* __restrict__ out,
                               const float* __restrict__ w, int len,
                               int in_stride, int out_stride)
{
    const int row = blockIdx.x;
    const float* ip = in + (size_t)row * in_stride;
    float* op = out + (size_t)row * out_stride;

    float ss = 0.f;
    for (int i = threadIdx.x; i < len; i += blockDim.x) {
        float v = ip[i];
        ss += v * v;
    }
    __shared__ float red[256];
    red[threadIdx.x] = ss;
    __syncthreads();
    #pragma unroll
    for (int s = 128; s > 0; s >>= 1) {
        if (threadIdx.x < s) red[threadIdx.x] += red[threadIdx.x + s];
        __syncthreads();
    }
    const float r = rsqrtf(red[0] / (float)len + 1e-6f);
    for (int i = threadIdx.x; i < len; i += blockDim.x) {
        float v = ip[i] * r;
        if (w) v *= w[i];
        op[i] = v;
    }
}

// ---------------- RoPE on q ----------------
// Reference quirk: q_rope is RESHAPED (b,s,h,dr)->(b,h,s,dr), so the effective
// rope position for original (s,h) is ((s*16 + h) mod 4096) + start_pos.
__global__ void rope_q_kernel(float* __restrict__ q, const int* __restrict__ start_pos)
{
    int idx = blockIdx.x * blockDim.x + threadIdx.x;
    if (idx >= T_TOKENS * NH * 32) return;
    const int i = idx & 31;
    const int h = (idx >> 5) & 15;
    const int t = idx >> 9;
    const int s = t & (SEQ - 1);
    const int pos = ((s * NH + h) & (SEQ - 1)) + start_pos[0];

    const float theta = powf(10000.0f, -(float)i * (1.0f / 32.0f));
    const float ang = (float)pos * theta;
    float sn, cs;
    sincosf(ang, &sn, &cs);

    float* base = q + (size_t)t * QDIM + h * HD + DN;
    const float x1 = base[i];
    const float x2 = base[i + 32];
    base[i]      = x1 * cs - x2 * sn;
    base[i + 32] = x2 * cs + x1 * sn;
}

// ---------------- RoPE on k_pe ----------------
// Reference quirk: k_pe goes through rope() with shape (b,s,1,dr), so
// seq_len==1 and EVERY token uses position == start_pos.
__global__ void rope_k_kernel(float* __restrict__ kv, const int* __restrict__ start_pos)
{
    int idx = blockIdx.x * blockDim.x + threadIdx.x;
    if (idx >= T_TOKENS * 32) return;
    const int i = idx & 31;
    const int t = idx >> 5;
    const int pos = start_pos[0];

    const float theta = powf(10000.0f, -(float)i * (1.0f / 32.0f));
    const float ang = (float)pos * theta;
    float sn, cs;
    sincosf(ang, &sn, &cs);

    float* base = kv + (size_t)t * KVA + KVL;
    const float x1 = base[i];
    const float x2 = base[i + 32];
    base[i]      = x1 * cs - x2 * sn;
    base[i + 32] = x2 * cs + x1 * sn;
}

// ---------------- per-token attention over heads (16x16) ----------------
// scores[qh,kh] = (q[t,qh,:] . k[t,kh,:]) / sqrt(192);  k = [k_nope | k_pe]
// context[t,qh,:] = softmax(scores) @ v
__global__ __launch_bounds__(512)
void attn_kernel(const float* __restrict__ q, const float* __restrict__ kvup,
                 const float* __restrict__ kv, float* __restrict__ ctx)
{
    const int t = blockIdx.x;
    __shared__ float ks[16][HD];   // 16 x 192
    __shared__ float vs[16][DV];   // 16 x 128

    const float* ku = kvup + (size_t)t * KVUPD;
    const float* pe = kv + (size_t)t * KVA + KVL;

    for (int idx = threadIdx.x; idx < 16 * 256; idx += blockDim.x) {
        const int kh = idx >> 8;
        const int c  = idx & 255;
        const float v = ku[idx];
        if (c < DN) ks[kh][c] = v;
        else        vs[kh][c - DN] = v;
    }
    for (int idx = threadIdx.x; idx < 16 * DR; idx += blockDim.x) {
        const int kh = idx >> 6;
        const int c  = idx & 63;
        ks[kh][DN + c] = pe[c];
    }
    __syncthreads();

    const int w    = threadIdx.x >> 5;   // q head
    const int lane = threadIdx.x & 31;
    const float* qr = q + (size_t)t * QDIM + w * HD;

    float qreg[6];
    #pragma unroll
    for (int e = 0; e < 6; e++) qreg[e] = qr[lane + 32 * e];

    float sc[16];
    #pragma unroll
    for (int kh = 0; kh < 16; kh++) {
        float p = 0.f;
        #pragma unroll
        for (int e = 0; e < 6; e++) p += qreg[e] * ks[kh][lane + 32 * e];
        #pragma unroll
        for (int o = 16; o > 0; o >>= 1) p += __shfl_xor_sync(0xffffffffu, p, o);
        sc[kh] = p * 0.07216878364870323f;   // 1/sqrt(192)
    }

    float m = sc[0];
    #pragma unroll
    for (int kh = 1; kh < 16; kh++) m = fmaxf(m, sc[kh]);
    float sum = 0.f;
    #pragma unroll
    for (int kh = 0; kh < 16; kh++) { sc[kh] = expf(sc[kh] - m); sum += sc[kh]; }
    const float inv = 1.f / sum;

    float acc[4] = {0.f, 0.f, 0.f, 0.f};
    #pragma unroll
    for (int kh = 0; kh < 16; kh++) {
        const float p = sc[kh] * inv;
        #pragma unroll
        for (int j = 0; j < 4; j++) acc[j] += p * vs[kh][lane + 32 * j];
    }

    float* o = ctx + (size_t)t * (NH * DV) + w * DV;
    #pragma unroll
    for (int j = 0; j < 4; j++) o[lane + 32 * j] = acc[j];
}

// ---------------- launcher ----------------
extern "C" void kernel_launch(void* const* d_in, const int* in_sizes, int n_in,
                              void* d_out, int out_size)
{
    const float* x        = (const float*)d_in[0];
    const float* wq_a     = (const float*)d_in[1];
    const float* q_norm_w = (const float*)d_in[2];
    const float* wq_b     = (const float*)d_in[3];
    const float* wkv_a    = (const float*)d_in[4];
    const float* wkv_b    = (const float*)d_in[5];
    const float* wo       = (const float*)d_in[6];
    const int*   start_pos = (const int*)d_in[7];
    float* out = (float*)d_out;

    float *qa, *qb, *kvb, *kvn, *kvup, *ctx;
    cudaGetSymbolAddress((void**)&qa,   g_qa);
    cudaGetSymbolAddress((void**)&qb,   g_q);
    cudaGetSymbolAddress((void**)&kvb,  g_kv);
    cudaGetSymbolAddress((void**)&kvn,  g_kvn);
    cudaGetSymbolAddress((void**)&kvup, g_kvup);
    cudaGetSymbolAddress((void**)&ctx,  g_ctx);

    const int MT = T_TOKENS / 128;   // 128 m-tiles

    // 1) q_a = x @ wq_a            [16384,2048] x [2048,1536]
    sgemm_kernel<<<dim3(QLORA / 128, MT), 256>>>(x, wq_a, qa, T_TOKENS, QLORA, DIM);
    // 2) rmsnorm(q_a) * q_norm_w   (in place)
    rmsnorm_kernel<<<T_TOKENS, 256>>>(qa, qa, q_norm_w, QLORA, QLORA, QLORA);
    // 3) q = q_a @ wq_b            [16384,1536] x [1536,3072]
    sgemm_kernel<<<dim3(QDIM / 128, MT), 256>>>(qa, wq_b, qb, T_TOKENS, QDIM, QLORA);
    // 4) kv = x @ wkv_a            [16384,2048] x [2048,576]  (N=576 -> 5 n-tiles)
    sgemm_kernel<<<dim3((KVA + 127) / 128, MT), 256>>>(x, wkv_a, kvb, T_TOKENS, KVA, DIM);
    // 5) RoPE
    rope_q_kernel<<<(T_TOKENS * NH * 32 + 255) / 256, 256>>>(qb, start_pos);
    rope_k_kernel<<<(T_TOKENS * 32 + 255) / 256, 256>>>(kvb, start_pos);
    // 6) kv_c rmsnorm (weight = 1) -> kvn
    rmsnorm_kernel<<<T_TOKENS, 256>>>(kvb, kvn, nullptr, KVL, KVA, KVL);
    // 7) kv_up = kvn @ wkv_b       [16384,512] x [512,4096]
    sgemm_kernel<<<dim3(KVUPD / 128, MT), 256>>>(kvn, wkv_b, kvup, T_TOKENS, KVUPD, KVL);
    // 8) per-token 16x16 attention -> ctx
    attn_kernel<<<T_TOKENS, 512>>>(qb, kvup, kvb, ctx);
    // 9) out = ctx @ wo            [16384,2048] x [2048,2048]
    sgemm_kernel<<<dim3(DIM / 128, MT), 256>>>(ctx, wo, out, T_TOKENS, DIM, DIM);
}

// round 3
// speedup vs baseline: 1.0015x; 1.0015x over previous
#include <cuda_runtime.h>

// ---------------- problem constants ----------------
#define T_TOKENS 16384      // b*s = 4*4096
#define SEQ      4096
#define DIM      2048
#define QLORA    1536
#define NH       16
#define DN       128
#define DR       64
#define DV       128
#define KVL      512
#define HD       192        // DN+DR
#define QDIM     3072       // NH*HD
#define KVA      576        // KVL+DR
#define KVUPD    4096       // NH*(DN+DV)

// ---------------- scratch (no allocs allowed) ----------------
__device__ float g_qa  [(size_t)T_TOKENS * QLORA];
__device__ float g_q   [(size_t)T_TOKENS * QDIM];
__device__ float g_kv  [(size_t)T_TOKENS * KVA];
__device__ float g_kvn [(size_t)T_TOKENS * KVL];
__device__ float g_kvup[(size_t)T_TOKENS * KVUPD];
__device__ float g_ctx [(size_t)T_TOKENS * (NH * DV)];

// ---------------- packed f32x2 helpers ----------------
__device__ __forceinline__ unsigned long long pack_dup(float a) {
    unsigned long long r;
    unsigned int ai = __float_as_uint(a);
    asm("mov.b64 %0, {%1, %1};" : "=l"(r) : "r"(ai));
    return r;
}
__device__ __forceinline__ void fma2(unsigned long long& c,
                                     unsigned long long a,
                                     unsigned long long b) {
    asm("fma.rn.f32x2 %0, %1, %2, %0;" : "+l"(c) : "l"(a), "l"(b));
}

// ---------------- SGEMM: C[M,N] = A[M,K] @ B[K,N], row-major ----------------
// BM=BN=128, BK=16, 256 threads, 8x8 per-thread, f32x2 packed accumulation.
// Requires: M % 128 == 0, K % 16 == 0, N % 8 == 0 (N may be non-mult of 128).
__global__ __launch_bounds__(256, 2)
void sgemm_kernel(const float* __restrict__ A, const float* __restrict__ B,
                  float* __restrict__ C, int M, int N, int K)
{
    __shared__ float As[16][132];   // transposed A tile, pad 4 for bank spread
    __shared__ float Bs[16][128];

    const int tid = threadIdx.x;
    const int tx  = tid & 15;       // n-direction (8 cols each)
    const int ty  = tid >> 4;       // m-direction (8 rows each)
    const int m0  = blockIdx.y << 7;
    const int n0  = blockIdx.x << 7;

    const int a_row = tid >> 2;          // 0..63  (x2 iterations)
    const int a_col = (tid & 3) << 2;    // 0,4,8,12
    const int b_row = tid >> 5;          // 0..7   (x2 iterations)
    const int b_col = (tid & 31) << 2;   // 0..124

    unsigned long long c2[8][4];
    #pragma unroll
    for (int i = 0; i < 8; i++)
        #pragma unroll
        for (int j = 0; j < 4; j++) c2[i][j] = 0ULL;

    for (int k0 = 0; k0 < K; k0 += 16) {
        #pragma unroll
        for (int r = 0; r < 2; r++) {
            int row = a_row + 64 * r;
            float4 av = *(const float4*)(A + (size_t)(m0 + row) * K + (k0 + a_col));
            As[a_col + 0][row] = av.x;
            As[a_col + 1][row] = av.y;
            As[a_col + 2][row] = av.z;
            As[a_col + 3][row] = av.w;
        }
        #pragma unroll
        for (int r = 0; r < 2; r++) {
            int row = b_row + 8 * r;
            int col = n0 + b_col;
            float4 bv = make_float4(0.f, 0.f, 0.f, 0.f);
            if (col < N)
                bv = *(const float4*)(B + (size_t)(k0 + row) * N + col);
            *(float4*)(&Bs[row][b_col]) = bv;
        }
        __syncthreads();

        #pragma unroll
        for (int k = 0; k < 16; k++) {
            float a[8];
            *(float4*)(&a[0]) = *(const float4*)(&As[k][ty * 8]);
            *(float4*)(&a[4]) = *(const float4*)(&As[k][ty * 8 + 4]);
            unsigned long long b2[4];
            const unsigned long long* bp =
                (const unsigned long long*)(&Bs[k][tx * 8]);
            #pragma unroll
            for (int j = 0; j < 4; j++) b2[j] = bp[j];
            #pragma unroll
            for (int i = 0; i < 8; i++) {
                unsigned long long a2 = pack_dup(a[i]);
                #pragma unroll
                for (int j = 0; j < 4; j++) fma2(c2[i][j], a2, b2[j]);
            }
        }
        __syncthreads();
    }

    const int col = n0 + tx * 8;
    if (col < N) {
        #pragma unroll
        for (int i = 0; i < 8; i++) {
            int row = m0 + ty * 8 + i;
            float2 f0 = *(float2*)&c2[i][0];
            float2 f1 = *(float2*)&c2[i][1];
            float2 f2 = *(float2*)&c2[i][2];
            float2 f3 = *(float2*)&c2[i][3];
            *(float4*)(C + (size_t)row * N + col)     = make_float4(f0.x, f0.y, f1.x, f1.y);
            *(float4*)(C + (size_t)row * N + col + 4) = make_float4(f2.x, f2.y, f3.x, f3.y);
        }
    }
}

// ---------------- RMSNorm (block per row) ----------------
__global__ void rmsnorm_kernel(const float* __restrict__ in, float* __restrict__ out,
                               const float* __restrict__ w, int len,
                               int in_stride, int out_stride)
{
    const int row = blockIdx.x;
    const float* ip = in + (size_t)row * in_stride;
    float* op = out + (size_t)row * out_stride;

    float ss = 0.f;
    for (int i = threadIdx.x; i < len; i += blockDim.x) {
        float v = ip[i];
        ss += v * v;
    }
    __shared__ float red[256];
    red[threadIdx.x] = ss;
    __syncthreads();
    #pragma unroll
    for (int s = 128; s > 0; s >>= 1) {
        if (threadIdx.x < s) red[threadIdx.x] += red[threadIdx.x + s];
        __syncthreads();
    }
    const float r = rsqrtf(red[0] / (float)len + 1e-6f);
    for (int i = threadIdx.x; i < len; i += blockDim.x) {
        float v = ip[i] * r;
        if (w) v *= w[i];
        op[i] = v;
    }
}

// ---------------- RoPE on q ----------------
// Reference quirk: q_rope is RESHAPED (b,s,h,dr)->(b,h,s,dr), so the effective
// rope position for original (s,h) is ((s*16 + h) mod 4096) + start_pos.
__global__ void rope_q_kernel(float* __restrict__ q, const int* __restrict__ start_pos)
{
    int idx = blockIdx.x * blockDim.x + threadIdx.x;
    if (idx >= T_TOKENS * NH * 32) return;
    const int i = idx & 31;
    const int h = (idx >> 5) & 15;
    const int t = idx >> 9;
    const int s = t & (SEQ - 1);
    const int pos = ((s * NH + h) & (SEQ - 1)) + start_pos[0];

    const float theta = powf(10000.0f, -(float)i * (1.0f / 32.0f));
    const float ang = (float)pos * theta;
    float sn, cs;
    sincosf(ang, &sn, &cs);

    float* base = q + (size_t)t * QDIM + h * HD + DN;
    const float x1 = base[i];
    const float x2 = base[i + 32];
    base[i]      = x1 * cs - x2 * sn;
    base[i + 32] = x2 * cs + x1 * sn;
}

// ---------------- RoPE on k_pe ----------------
// Reference quirk: k_pe goes through rope() with shape (b,s,1,dr), so
// seq_len==1 and EVERY token uses position == start_pos.
__global__ void rope_k_kernel(float* __restrict__ kv, const int* __restrict__ start_pos)
{
    int idx = blockIdx.x * blockDim.x + threadIdx.x;
    if (idx >= T_TOKENS * 32) return;
    const int i = idx & 31;
    const int t = idx >> 5;
    const int pos = start_pos[0];

    const float theta = powf(10000.0f, -(float)i * (1.0f / 32.0f));
    const float ang = (float)pos * theta;
    float sn, cs;
    sincosf(ang, &sn, &cs);

    float* base = kv + (size_t)t * KVA + KVL;
    const float x1 = base[i];
    const float x2 = base[i + 32];
    base[i]      = x1 * cs - x2 * sn;
    base[i + 32] = x2 * cs + x1 * sn;
}

// ---------------- per-token attention over heads (16x16) ----------------
// scores[qh,kh] = (q[t,qh,:] . k[t,kh,:]) / sqrt(192);  k = [k_nope | k_pe]
// context[t,qh,:] = softmax(scores) @ v
__global__ __launch_bounds__(512)
void attn_kernel(const float* __restrict__ q, const float* __restrict__ kvup,
                 const float* __restrict__ kv, float* __restrict__ ctx)
{
    const int t = blockIdx.x;
    __shared__ float ks[16][HD];   // 16 x 192
    __shared__ float vs[16][DV];   // 16 x 128

    const float* ku = kvup + (size_t)t * KVUPD;
    const float* pe = kv + (size_t)t * KVA + KVL;

    for (int idx = threadIdx.x; idx < 16 * 256; idx += blockDim.x) {
        const int kh = idx >> 8;
        const int c  = idx & 255;
        const float v = ku[idx];
        if (c < DN) ks[kh][c] = v;
        else        vs[kh][c - DN] = v;
    }
    for (int idx = threadIdx.x; idx < 16 * DR; idx += blockDim.x) {
        const int kh = idx >> 6;
        const int c  = idx & 63;
        ks[kh][DN + c] = pe[c];
    }
    __syncthreads();

    const int w    = threadIdx.x >> 5;   // q head
    const int lane = threadIdx.x & 31;
    const float* qr = q + (size_t)t * QDIM + w * HD;

    float qreg[6];
    #pragma unroll
    for (int e = 0; e < 6; e++) qreg[e] = qr[lane + 32 * e];

    float sc[16];
    #pragma unroll
    for (int kh = 0; kh < 16; kh++) {
        float p = 0.f;
        #pragma unroll
        for (int e = 0; e < 6; e++) p += qreg[e] * ks[kh][lane + 32 * e];
        #pragma unroll
        for (int o = 16; o > 0; o >>= 1) p += __shfl_xor_sync(0xffffffffu, p, o);
        sc[kh] = p * 0.07216878364870323f;   // 1/sqrt(192)
    }

    float m = sc[0];
    #pragma unroll
    for (int kh = 1; kh < 16; kh++) m = fmaxf(m, sc[kh]);
    float sum = 0.f;
    #pragma unroll
    for (int kh = 0; kh < 16; kh++) { sc[kh] = expf(sc[kh] - m); sum += sc[kh]; }
    const float inv = 1.f / sum;

    float acc[4] = {0.f, 0.f, 0.f, 0.f};
    #pragma unroll
    for (int kh = 0; kh < 16; kh++) {
        const float p = sc[kh] * inv;
        #pragma unroll
        for (int j = 0; j < 4; j++) acc[j] += p * vs[kh][lane + 32 * j];
    }

    float* o = ctx + (size_t)t * (NH * DV) + w * DV;
    #pragma unroll
    for (int j = 0; j < 4; j++) o[lane + 32 * j] = acc[j];
}

// ---------------- launcher ----------------
extern "C" void kernel_launch(void* const* d_in, const int* in_sizes, int n_in,
                              void* d_out, int out_size)
{
    const float* x        = (const float*)d_in[0];
    const float* wq_a     = (const float*)d_in[1];
    const float* q_norm_w = (const float*)d_in[2];
    const float* wq_b     = (const float*)d_in[3];
    const float* wkv_a    = (const float*)d_in[4];
    const float* wkv_b    = (const float*)d_in[5];
    const float* wo       = (const float*)d_in[6];
    const int*   start_pos = (const int*)d_in[7];
    float* out = (float*)d_out;

    float *qa, *qb, *kvb, *kvn, *kvup, *ctx;
    cudaGetSymbolAddress((void**)&qa,   g_qa);
    cudaGetSymbolAddress((void**)&qb,   g_q);
    cudaGetSymbolAddress((void**)&kvb,  g_kv);
    cudaGetSymbolAddress((void**)&kvn,  g_kvn);
    cudaGetSymbolAddress((void**)&kvup, g_kvup);
    cudaGetSymbolAddress((void**)&ctx,  g_ctx);

    const int MT = T_TOKENS / 128;   // 128 m-tiles

    // 1) q_a = x @ wq_a            [16384,2048] x [2048,1536]
    sgemm_kernel<<<dim3(QLORA / 128, MT), 256>>>(x, wq_a, qa, T_TOKENS, QLORA, DIM);
    // 2) rmsnorm(q_a) * q_norm_w   (in place)
    rmsnorm_kernel<<<T_TOKENS, 256>>>(qa, qa, q_norm_w, QLORA, QLORA, QLORA);
    // 3) q = q_a @ wq_b            [16384,1536] x [1536,3072]
    sgemm_kernel<<<dim3(QDIM / 128, MT), 256>>>(qa, wq_b, qb, T_TOKENS, QDIM, QLORA);
    // 4) kv = x @ wkv_a            [16384,2048] x [2048,576]  (N=576 -> 5 n-tiles)
    sgemm_kernel<<<dim3((KVA + 127) / 128, MT), 256>>>(x, wkv_a, kvb, T_TOKENS, KVA, DIM);
    // 5) RoPE
    rope_q_kernel<<<(T_TOKENS * NH * 32 + 255) / 256, 256>>>(qb, start_pos);
    rope_k_kernel<<<(T_TOKENS * 32 + 255) / 256, 256>>>(kvb, start_pos);
    // 6) kv_c rmsnorm (weight = 1) -> kvn
    rmsnorm_kernel<<<T_TOKENS, 256>>>(kvb, kvn, nullptr, KVL, KVA, KVL);
    // 7) kv_up = kvn @ wkv_b       [16384,512] x [512,4096]
    sgemm_kernel<<<dim3(KVUPD / 128, MT), 256>>>(kvn, wkv_b, kvup, T_TOKENS, KVUPD, KVL);
    // 8) per-token 16x16 attention -> ctx
    attn_kernel<<<T_TOKENS, 512>>>(qb, kvup, kvb, ctx);
    // 9) out = ctx @ wo            [16384,2048] x [2048,2048]
    sgemm_kernel<<<dim3(DIM / 128, MT), 256>>>(ctx, wo, out, T_TOKENS, DIM, DIM);
}